// round 7
// baseline (speedup 1.0000x reference)
#include <cuda_runtime.h>
#include <cuda_fp16.h>
#include <math.h>
#include <stdint.h>

// Problem constants
#define B_     8
#define CIN_   64
#define COUT_  128
#define KH_    3
#define KW_    3
#define K_     9
#define H_     64
#define W_     64
#define P_     4096        // H*W
#define CK_    576         // CIN*K
#define KP_    288         // CK/2 k-pairs

// Scratch (static __device__ -> allocation-guard safe)
__device__ float     g_rgbt[B_ * P_ * CIN_];     // [b][p][c]  8.4 MB
__device__ __half    g_colh[B_ * CK_ * P_];      // fp16 col, ck' = k*64+c (37.7 MB)
__device__ uint32_t  g_wt[KP_ * COUT_];          // weight packed half2 (kpair, m_perm)

__device__ __forceinline__ int mperm(int m) {
    return (m & ~15) | (((m & 7) << 1) | ((m >> 3) & 1));
}

// ---------------------------------------------------------------------------
// Kernel 0 (merged): blocks [0,512) transpose rgb -> rgb_t;
//                    blocks [512,656) pack weight to half2 (kpair, m_perm).
// ---------------------------------------------------------------------------
__global__ __launch_bounds__(256)
void prep_kernel(const float* __restrict__ rgb,
                 const float* __restrict__ weight) {
    const int bid = blockIdx.x;
    const int tid = threadIdx.x;

    if (bid < 512) {
        __shared__ float ts[64][65];
        const int b     = bid >> 6;
        const int pbase = (bid & 63) * 64;
        {
            int pp   = tid & 63;
            int crow = tid >> 6;
            const float* src = rgb + ((size_t)b * CIN_) * P_ + pbase + pp;
            #pragma unroll
            for (int r = 0; r < 16; r++) {
                int c = crow * 16 + r;
                ts[c][pp] = src[(size_t)c * P_];
            }
        }
        __syncthreads();
        {
            int cc   = tid & 63;
            int prow = tid >> 6;
            float* dst = g_rgbt + ((size_t)b * P_ + pbase) * CIN_ + cc;
            #pragma unroll
            for (int r = 0; r < 16; r++) {
                int p = prow * 16 + r;
                dst[(size_t)p * CIN_] = ts[cc][p];
            }
        }
    } else {
        int idx = (bid - 512) * 256 + tid;     // exactly KP_*COUT_ = 36864
        int m  = idx & 127;
        int kp = idx >> 7;
        int ck0 = 2 * kp, ck1 = 2 * kp + 1;
        int k0 = ck0 >> 6, c0 = ck0 & 63;
        int k1 = ck1 >> 6, c1 = ck1 & 63;
        __half h0 = __float2half(weight[(size_t)m * CK_ + c0 * K_ + k0]);
        __half h1 = __float2half(weight[(size_t)m * CK_ + c1 * K_ + k1]);
        uint32_t u = (uint32_t)__half_as_ushort(h0) |
                     ((uint32_t)__half_as_ushort(h1) << 16);
        g_wt[(size_t)kp * COUT_ + mperm(m)] = u;
    }
}

// ---------------------------------------------------------------------------
// Kernel 1: deformable im2col v4.
// Block = (b, k, 128-pixel tile). Phase1: meta. Phase2: warp-per-pixel
// coalesced channel gathers from rgb_t. Phase3: smem transpose -> col[ck'][p].
// ---------------------------------------------------------------------------
#define PT 128      // pixels per block

__global__ __launch_bounds__(256)
void im2col_kernel(const float* __restrict__ offsets) {
    __shared__ float4 metaW[PT];
    __shared__ int4   metaI[PT];
    __shared__ __half res[PT][72];     // [pixel][channel], 72-pad (144B rows)

    const int ptile = blockIdx.x;
    const int k     = blockIdx.y;
    const int b     = blockIdx.z;
    const int p0    = ptile * PT;
    const int tid   = threadIdx.x;
    const int lane  = tid & 31;
    const int w     = tid >> 5;

    // ---- Phase 1: bilinear meta for 128 pixels ----
    if (tid < PT) {
        int p  = p0 + tid;
        int oy = p >> 6;
        int ox = p & 63;

        const float* offb = offsets + (size_t)b * 2 * K_ * P_;
        float dy = offb[(2 * k    ) * P_ + p];
        float dx = offb[(2 * k + 1) * P_ + p];

        float y = (float)(oy - 1 + k / KW_) + dy;
        float x = (float)(ox - 1 + k % KW_) + dx;

        float y0f = floorf(y), x0f = floorf(x);
        float fy = y - y0f,    fx = x - x0f;
        int y0 = (int)y0f, x0 = (int)x0f;
        int y1 = y0 + 1,   x1 = x0 + 1;

        float w00 = (1.f - fy) * (1.f - fx);
        float w01 = (1.f - fy) * fx;
        float w10 = fy * (1.f - fx);
        float w11 = fy * fx;

        bool vy0 = (y0 >= 0) & (y0 < H_);
        bool vy1 = (y1 >= 0) & (y1 < H_);
        bool vx0 = (x0 >= 0) & (x0 < W_);
        bool vx1 = (x1 >= 0) & (x1 < W_);
        if (!(vy0 & vx0)) w00 = 0.f;
        if (!(vy0 & vx1)) w01 = 0.f;
        if (!(vy1 & vx0)) w10 = 0.f;
        if (!(vy1 & vx1)) w11 = 0.f;

        int cy0 = min(max(y0, 0), H_ - 1);
        int cy1 = min(max(y1, 0), H_ - 1);
        int cx0 = min(max(x0, 0), W_ - 1);
        int cx1 = min(max(x1, 0), W_ - 1);

        metaW[tid] = make_float4(w00, w01, w10, w11);
        metaI[tid] = make_int4(cy0 * W_ + cx0, cy0 * W_ + cx1,
                               cy1 * W_ + cx0, cy1 * W_ + cx1);
    }
    __syncthreads();

    // ---- Phase 2: warp-per-pixel gather (lane = channel pair) ----
    const float* base = g_rgbt + (size_t)b * P_ * CIN_;
    #pragma unroll 4
    for (int i = 0; i < 16; i++) {
        int px = w * 16 + i;
        float4 wt = metaW[px];
        int4   ix = metaI[px];
        float2 q00 = ((const float2*)(base + (size_t)ix.x * CIN_))[lane];
        float2 q01 = ((const float2*)(base + (size_t)ix.y * CIN_))[lane];
        float2 q10 = ((const float2*)(base + (size_t)ix.z * CIN_))[lane];
        float2 q11 = ((const float2*)(base + (size_t)ix.w * CIN_))[lane];
        float vx = wt.x * q00.x + wt.y * q01.x + wt.z * q10.x + wt.w * q11.x;
        float vy = wt.x * q00.y + wt.y * q01.y + wt.z * q10.y + wt.w * q11.y;
        *(__half2*)&res[px][2 * lane] = __floats2half2_rn(vx, vy);
    }
    __syncthreads();

    // ---- Phase 3: transpose out, coalesced STG.128 into col[ck'][p] ----
    __half* colb = g_colh + ((size_t)(b * CK_ + k * 64)) * P_ + p0;
    #pragma unroll
    for (int j = 0; j < 4; j++) {
        int lin = j * 256 + tid;       // 0..1023
        int c   = lin >> 4;            // 0..63
        int seg = lin & 15;            // pixels seg*8 .. seg*8+7
        __align__(16) __half tmp[8];
        #pragma unroll
        for (int t = 0; t < 8; t++)
            tmp[t] = res[seg * 8 + t][c];
        *(uint4*)&colb[(size_t)c * P_ + seg * 8] = *(uint4*)tmp;
    }
}

// ---------------------------------------------------------------------------
// Kernel 2: FP16 tensor-core GEMM (m16n8k16, fp32 accum).  (unchanged)
// ---------------------------------------------------------------------------
#define BN 128
#define NKP 8
#define LDA 136

__global__ __launch_bounds__(256)
void gemm_fp16_kernel(const float* __restrict__ bias,
                      float* __restrict__ out) {
    __shared__ uint32_t As[NKP][LDA];
    __shared__ uint32_t Bs[NKP][LDA];

    const int b   = blockIdx.z;
    const int n0  = blockIdx.x * BN;
    const int tid = threadIdx.x;
    const int lane = tid & 31;
    const int wid  = tid >> 5;
    const int m_off = (wid >> 2) * 64;
    const int n_off = (wid & 3) * 32;
    const int qq = lane >> 2;
    const int rr = lane & 3;

    const __half* colb = g_colh + (size_t)b * CK_ * P_;
    const uint4*  wt4  = (const uint4*)g_wt;

    const int prow = wid;
    const int pseg = lane;

    float acc[4][4][4];
    #pragma unroll
    for (int i = 0; i < 4; i++)
        #pragma unroll
        for (int j = 0; j < 4; j++)
            #pragma unroll
            for (int c = 0; c < 4; c++) acc[i][j][c] = 0.f;

    uint4 pa;
    uint2 blo, bhi;
    {
        pa  = wt4[(size_t)prow * 32 + pseg];
        const __half* r0 = colb + (size_t)(2 * prow    ) * P_ + n0 + pseg * 4;
        const __half* r1 = colb + (size_t)(2 * prow + 1) * P_ + n0 + pseg * 4;
        blo = *(const uint2*)r0;
        bhi = *(const uint2*)r1;
    }

    for (int kp0 = 0; kp0 < KP_; kp0 += NKP) {
        *(uint4*)&As[prow][pseg * 4] = pa;
        uint32_t b0 = __byte_perm(blo.x, bhi.x, 0x5410);
        uint32_t b1 = __byte_perm(blo.x, bhi.x, 0x7632);
        uint32_t b2 = __byte_perm(blo.y, bhi.y, 0x5410);
        uint32_t b3 = __byte_perm(blo.y, bhi.y, 0x7632);
        *(uint4*)&Bs[prow][pseg * 4] = make_uint4(b0, b1, b2, b3);
        __syncthreads();

        if (kp0 + NKP < KP_) {
            int kr = kp0 + NKP + prow;
            pa = wt4[(size_t)kr * 32 + pseg];
            const __half* r0 = colb + (size_t)(2 * kr    ) * P_ + n0 + pseg * 4;
            const __half* r1 = colb + (size_t)(2 * kr + 1) * P_ + n0 + pseg * 4;
            blo = *(const uint2*)r0;
            bhi = *(const uint2*)r1;
        }

        uint32_t bf[4][2];
        #pragma unroll
        for (int bn = 0; bn < 4; bn++) {
            bf[bn][0] = Bs[rr    ][n_off + 8 * bn + qq];
            bf[bn][1] = Bs[rr + 4][n_off + 8 * bn + qq];
        }
        uint32_t af[4][4];
        #pragma unroll
        for (int am = 0; am < 4; am++) {
            uint2 v0 = *(const uint2*)&As[rr    ][m_off + 16 * am + 2 * qq];
            uint2 v1 = *(const uint2*)&As[rr + 4][m_off + 16 * am + 2 * qq];
            af[am][0] = v0.x; af[am][1] = v0.y;
            af[am][2] = v1.x; af[am][3] = v1.y;
        }
        #pragma unroll
        for (int am = 0; am < 4; am++)
            #pragma unroll
            for (int bn = 0; bn < 4; bn++) {
                asm volatile(
                    "mma.sync.aligned.m16n8k16.row.col.f32.f16.f16.f32 "
                    "{%0,%1,%2,%3}, {%4,%5,%6,%7}, {%8,%9}, {%0,%1,%2,%3};"
                    : "+f"(acc[am][bn][0]), "+f"(acc[am][bn][1]),
                      "+f"(acc[am][bn][2]), "+f"(acc[am][bn][3])
                    : "r"(af[am][0]), "r"(af[am][1]),
                      "r"(af[am][2]), "r"(af[am][3]),
                      "r"(bf[bn][0]), "r"(bf[bn][1]));
            }
        __syncthreads();
    }

    float* outb = out + (size_t)b * COUT_ * P_;
    #pragma unroll
    for (int am = 0; am < 4; am++) {
        int m0r = m_off + 16 * am + qq;
        float bv0 = bias[m0r];
        float bv1 = bias[m0r + 8];
        #pragma unroll
        for (int bn = 0; bn < 4; bn++) {
            int col = n0 + n_off + 8 * bn + 2 * rr;
            float2 v0 = make_float2(acc[am][bn][0] + bv0, acc[am][bn][1] + bv0);
            float2 v1 = make_float2(acc[am][bn][2] + bv1, acc[am][bn][3] + bv1);
            *(float2*)&outb[(size_t)m0r * P_ + col]       = v0;
            *(float2*)&outb[(size_t)(m0r + 8) * P_ + col] = v1;
        }
    }
}

extern "C" void kernel_launch(void* const* d_in, const int* in_sizes, int n_in,
                              void* d_out, int out_size) {
    const float* rgb     = (const float*)d_in[0];
    const float* offsets = (const float*)d_in[1];
    const float* weight  = (const float*)d_in[2];
    const float* bias    = (const float*)d_in[3];
    float* out = (float*)d_out;

    prep_kernel<<<656, 256>>>(rgb, weight);
    {
        dim3 grid(P_ / PT, K_, B_);          // 32 x 9 x 8 = 2304 blocks
        im2col_kernel<<<grid, 256>>>(offsets);
    }
    {
        dim3 grid(P_ / BN, 1, B_);           // 32 x 1 x 8
        gemm_fp16_kernel<<<grid, 256>>>(bias, out);
    }
}

// round 8
// speedup vs baseline: 1.7124x; 1.7124x over previous
#include <cuda_runtime.h>
#include <cuda_fp16.h>
#include <math.h>
#include <stdint.h>

// Problem constants
#define B_     8
#define CIN_   64
#define COUT_  128
#define KH_    3
#define KW_    3
#define K_     9
#define H_     64
#define W_     64
#define P_     4096        // H*W
#define CK_    576         // CIN*K
#define KP_    288         // CK/2 k-pairs

// Scratch (static __device__ -> allocation-guard safe)
__device__ __half    g_rgbth[B_ * P_ * CIN_];    // fp16 [b][p][c]  4.2 MB
__device__ __half    g_colh[B_ * P_ * CK_];      // fp16 col [b][p][ck'], ck'=k*64+c
__device__ uint32_t  g_wt[KP_ * COUT_];          // weight packed half2 (kpair, m_perm)

__device__ __forceinline__ int mperm(int m) {
    return (m & ~15) | (((m & 7) << 1) | ((m >> 3) & 1));
}

// ---------------------------------------------------------------------------
// Kernel 0 (merged): blocks [0,512) transpose rgb fp32 [c][p] -> fp16 [p][c];
//                    blocks [512,656) pack weight to half2 (kpair, m_perm).
// ---------------------------------------------------------------------------
__global__ __launch_bounds__(256)
void prep_kernel(const float* __restrict__ rgb,
                 const float* __restrict__ weight) {
    const int bid = blockIdx.x;
    const int tid = threadIdx.x;

    if (bid < 512) {
        __shared__ float ts[64][65];
        const int b     = bid >> 6;
        const int pbase = (bid & 63) * 64;
        {
            int pp   = tid & 63;
            int crow = tid >> 6;
            const float* src = rgb + ((size_t)b * CIN_) * P_ + pbase + pp;
            #pragma unroll
            for (int r = 0; r < 16; r++) {
                int c = crow * 16 + r;
                ts[c][pp] = src[(size_t)c * P_];
            }
        }
        __syncthreads();
        {
            int cc   = tid & 63;
            int prow = tid >> 6;
            __half* dst = g_rgbth + ((size_t)b * P_ + pbase) * CIN_ + cc;
            #pragma unroll
            for (int r = 0; r < 16; r++) {
                int p = prow * 16 + r;
                dst[(size_t)p * CIN_] = __float2half(ts[cc][p]);
            }
        }
    } else {
        int idx = (bid - 512) * 256 + tid;     // exactly KP_*COUT_ = 36864
        int m  = idx & 127;
        int kp = idx >> 7;
        int ck0 = 2 * kp, ck1 = 2 * kp + 1;
        int k0 = ck0 >> 6, c0 = ck0 & 63;
        int k1 = ck1 >> 6, c1 = ck1 & 63;
        __half h0 = __float2half(weight[(size_t)m * CK_ + c0 * K_ + k0]);
        __half h1 = __float2half(weight[(size_t)m * CK_ + c1 * K_ + k1]);
        uint32_t u = (uint32_t)__half_as_ushort(h0) |
                     ((uint32_t)__half_as_ushort(h1) << 16);
        g_wt[(size_t)kp * COUT_ + mperm(m)] = u;
    }
}

// ---------------------------------------------------------------------------
// Kernel 1: deformable im2col v5.
// Block = (b, k, 128-pixel tile). Warp-per-pixel, lane = channel pair.
// Each corner read = one 128B line from fp16 rgb_t; result stored directly
// as one 128B line of col[b][p][k*64 .. k*64+64). No smem staging.
// ---------------------------------------------------------------------------
#define PT 128      // pixels per block

__global__ __launch_bounds__(256)
void im2col_kernel(const float* __restrict__ offsets) {
    __shared__ float4 metaW[PT];
    __shared__ int4   metaI[PT];

    const int ptile = blockIdx.x;
    const int k     = blockIdx.y;
    const int b     = blockIdx.z;
    const int p0    = ptile * PT;
    const int tid   = threadIdx.x;
    const int lane  = tid & 31;
    const int w     = tid >> 5;

    // ---- Phase 1: bilinear meta for 128 pixels ----
    if (tid < PT) {
        int p  = p0 + tid;
        int oy = p >> 6;
        int ox = p & 63;

        const float* offb = offsets + (size_t)b * 2 * K_ * P_;
        float dy = offb[(2 * k    ) * P_ + p];
        float dx = offb[(2 * k + 1) * P_ + p];

        float y = (float)(oy - 1 + k / KW_) + dy;
        float x = (float)(ox - 1 + k % KW_) + dx;

        float y0f = floorf(y), x0f = floorf(x);
        float fy = y - y0f,    fx = x - x0f;
        int y0 = (int)y0f, x0 = (int)x0f;
        int y1 = y0 + 1,   x1 = x0 + 1;

        float w00 = (1.f - fy) * (1.f - fx);
        float w01 = (1.f - fy) * fx;
        float w10 = fy * (1.f - fx);
        float w11 = fy * fx;

        bool vy0 = (y0 >= 0) & (y0 < H_);
        bool vy1 = (y1 >= 0) & (y1 < H_);
        bool vx0 = (x0 >= 0) & (x0 < W_);
        bool vx1 = (x1 >= 0) & (x1 < W_);
        if (!(vy0 & vx0)) w00 = 0.f;
        if (!(vy0 & vx1)) w01 = 0.f;
        if (!(vy1 & vx0)) w10 = 0.f;
        if (!(vy1 & vx1)) w11 = 0.f;

        int cy0 = min(max(y0, 0), H_ - 1);
        int cy1 = min(max(y1, 0), H_ - 1);
        int cx0 = min(max(x0, 0), W_ - 1);
        int cx1 = min(max(x1, 0), W_ - 1);

        metaW[tid] = make_float4(w00, w01, w10, w11);
        metaI[tid] = make_int4(cy0 * W_ + cx0, cy0 * W_ + cx1,
                               cy1 * W_ + cx0, cy1 * W_ + cx1);
    }
    __syncthreads();

    // ---- Phase 2: gather + direct gmem store ----
    const __half* baseh = g_rgbth + (size_t)b * P_ * CIN_;
    #pragma unroll 4
    for (int i = 0; i < 16; i++) {
        int px = w * 16 + i;
        int p  = p0 + px;
        float4 wt = metaW[px];
        int4   ix = metaI[px];
        __half2 q00 = ((const __half2*)(baseh + (size_t)ix.x * CIN_))[lane];
        __half2 q01 = ((const __half2*)(baseh + (size_t)ix.y * CIN_))[lane];
        __half2 q10 = ((const __half2*)(baseh + (size_t)ix.z * CIN_))[lane];
        __half2 q11 = ((const __half2*)(baseh + (size_t)ix.w * CIN_))[lane];
        float2 f00 = __half22float2(q00);
        float2 f01 = __half22float2(q01);
        float2 f10 = __half22float2(q10);
        float2 f11 = __half22float2(q11);
        float vx = wt.x * f00.x + wt.y * f01.x + wt.z * f10.x + wt.w * f11.x;
        float vy = wt.x * f00.y + wt.y * f01.y + wt.z * f10.y + wt.w * f11.y;
        __half2* dst = (__half2*)(g_colh + ((size_t)b * P_ + p) * CK_ + k * 64);
        dst[lane] = __floats2half2_rn(vx, vy);
    }
}

// ---------------------------------------------------------------------------
// Kernel 2: FP16 tensor-core GEMM (m16n8k16, fp32 accum).
// B read from pixel-major col: k-pairs already adjacent, no repacking.
// ---------------------------------------------------------------------------
#define BN 128
#define NKP 8
#define LDA 136

__global__ __launch_bounds__(256)
void gemm_fp16_kernel(const float* __restrict__ bias,
                      float* __restrict__ out) {
    __shared__ uint32_t As[NKP][LDA];
    __shared__ uint32_t Bs[NKP][LDA];

    const int b   = blockIdx.z;
    const int n0  = blockIdx.x * BN;
    const int tid = threadIdx.x;
    const int lane = tid & 31;
    const int wid  = tid >> 5;
    const int m_off = (wid >> 2) * 64;
    const int n_off = (wid & 3) * 32;
    const int qq = lane >> 2;
    const int rr = lane & 3;

    const __half* colb = g_colh + (size_t)b * P_ * CK_;   // [p][ck']
    const uint4*  wt4  = (const uint4*)g_wt;

    // producers
    const int prow = wid;            // A: kpair row 0..7
    const int pseg = lane;           // A: 4-col segment
    const int bpx  = tid >> 1;       // B: pixel 0..127
    const int bseg = tid & 1;        // B: which 16B half of the 32B k-slice

    float acc[4][4][4];
    #pragma unroll
    for (int i = 0; i < 4; i++)
        #pragma unroll
        for (int j = 0; j < 4; j++)
            #pragma unroll
            for (int c = 0; c < 4; c++) acc[i][j][c] = 0.f;

    // prefetch tile 0
    uint4 pa = wt4[(size_t)prow * 32 + pseg];
    uint4 pb = *(const uint4*)(colb + (size_t)(n0 + bpx) * CK_ + bseg * 8);

    for (int kp0 = 0; kp0 < KP_; kp0 += NKP) {
        *(uint4*)&As[prow][pseg * 4] = pa;
        Bs[bseg * 4 + 0][bpx] = pb.x;
        Bs[bseg * 4 + 1][bpx] = pb.y;
        Bs[bseg * 4 + 2][bpx] = pb.z;
        Bs[bseg * 4 + 3][bpx] = pb.w;
        __syncthreads();

        if (kp0 + NKP < KP_) {
            int kr = kp0 + NKP;
            pa = wt4[(size_t)(kr + prow) * 32 + pseg];
            pb = *(const uint4*)(colb + (size_t)(n0 + bpx) * CK_
                                 + kr * 2 + bseg * 8);
        }

        uint32_t bf[4][2];
        #pragma unroll
        for (int bn = 0; bn < 4; bn++) {
            bf[bn][0] = Bs[rr    ][n_off + 8 * bn + qq];
            bf[bn][1] = Bs[rr + 4][n_off + 8 * bn + qq];
        }
        uint32_t af[4][4];
        #pragma unroll
        for (int am = 0; am < 4; am++) {
            uint2 v0 = *(const uint2*)&As[rr    ][m_off + 16 * am + 2 * qq];
            uint2 v1 = *(const uint2*)&As[rr + 4][m_off + 16 * am + 2 * qq];
            af[am][0] = v0.x; af[am][1] = v0.y;
            af[am][2] = v1.x; af[am][3] = v1.y;
        }
        #pragma unroll
        for (int am = 0; am < 4; am++)
            #pragma unroll
            for (int bn = 0; bn < 4; bn++) {
                asm volatile(
                    "mma.sync.aligned.m16n8k16.row.col.f32.f16.f16.f32 "
                    "{%0,%1,%2,%3}, {%4,%5,%6,%7}, {%8,%9}, {%0,%1,%2,%3};"
                    : "+f"(acc[am][bn][0]), "+f"(acc[am][bn][1]),
                      "+f"(acc[am][bn][2]), "+f"(acc[am][bn][3])
                    : "r"(af[am][0]), "r"(af[am][1]),
                      "r"(af[am][2]), "r"(af[am][3]),
                      "r"(bf[bn][0]), "r"(bf[bn][1]));
            }
        __syncthreads();
    }

    float* outb = out + (size_t)b * COUT_ * P_;
    #pragma unroll
    for (int am = 0; am < 4; am++) {
        int m0r = m_off + 16 * am + qq;
        float bv0 = bias[m0r];
        float bv1 = bias[m0r + 8];
        #pragma unroll
        for (int bn = 0; bn < 4; bn++) {
            int col = n0 + n_off + 8 * bn + 2 * rr;
            float2 v0 = make_float2(acc[am][bn][0] + bv0, acc[am][bn][1] + bv0);
            float2 v1 = make_float2(acc[am][bn][2] + bv1, acc[am][bn][3] + bv1);
            *(float2*)&outb[(size_t)m0r * P_ + col]       = v0;
            *(float2*)&outb[(size_t)(m0r + 8) * P_ + col] = v1;
        }
    }
}

extern "C" void kernel_launch(void* const* d_in, const int* in_sizes, int n_in,
                              void* d_out, int out_size) {
    const float* rgb     = (const float*)d_in[0];
    const float* offsets = (const float*)d_in[1];
    const float* weight  = (const float*)d_in[2];
    const float* bias    = (const float*)d_in[3];
    float* out = (float*)d_out;

    prep_kernel<<<656, 256>>>(rgb, weight);
    {
        dim3 grid(P_ / PT, K_, B_);          // 32 x 9 x 8 = 2304 blocks
        im2col_kernel<<<grid, 256>>>(offsets);
    }
    {
        dim3 grid(P_ / BN, 1, B_);           // 32 x 1 x 8
        gemm_fp16_kernel<<<grid, 256>>>(bias, out);
    }
}

// round 9
// speedup vs baseline: 1.8071x; 1.0553x over previous
#include <cuda_runtime.h>
#include <cuda_fp16.h>
#include <math.h>
#include <stdint.h>

// Problem constants
#define B_     8
#define CIN_   64
#define COUT_  128
#define KH_    3
#define KW_    3
#define K_     9
#define H_     64
#define W_     64
#define P_     4096        // H*W
#define CK_    576         // CIN*K
#define KP_    288         // CK/2 k-pairs

// Scratch (static __device__ -> allocation-guard safe)
__device__ __half    g_rgbth[B_ * P_ * CIN_];    // fp16 [b][p][c]  4.2 MB
__device__ __half    g_colh[B_ * P_ * CK_];      // fp16 col [b][p][ck'], ck'=k*64+c
__device__ uint32_t  g_wt[KP_ * COUT_];          // weight packed half2 (kpair, m_perm)

__device__ __forceinline__ int mperm(int m) {
    return (m & ~15) | (((m & 7) << 1) | ((m >> 3) & 1));
}

__device__ __forceinline__ void cp16(uint32_t smem_addr, const void* gptr) {
    asm volatile("cp.async.ca.shared.global [%0], [%1], 16;"
                 :: "r"(smem_addr), "l"(gptr));
}
__device__ __forceinline__ void cp_commit() {
    asm volatile("cp.async.commit_group;");
}
template<int N>
__device__ __forceinline__ void cp_wait() {
    asm volatile("cp.async.wait_group %0;" :: "n"(N));
}

// ---------------------------------------------------------------------------
// Kernel 0 (merged): blocks [0,512) transpose rgb fp32 [c][p] -> fp16 [p][c];
//                    blocks [512,656) pack weight to half2 (kpair, m_perm).
// ---------------------------------------------------------------------------
__global__ __launch_bounds__(256)
void prep_kernel(const float* __restrict__ rgb,
                 const float* __restrict__ weight) {
    const int bid = blockIdx.x;
    const int tid = threadIdx.x;

    if (bid < 512) {
        __shared__ float ts[64][65];
        const int b     = bid >> 6;
        const int pbase = (bid & 63) * 64;
        {
            int pp   = tid & 63;
            int crow = tid >> 6;
            const float* src = rgb + ((size_t)b * CIN_) * P_ + pbase + pp;
            #pragma unroll
            for (int r = 0; r < 16; r++) {
                int c = crow * 16 + r;
                ts[c][pp] = src[(size_t)c * P_];
            }
        }
        __syncthreads();
        {
            int c2   = tid & 31;        // channel pair
            int prow = tid >> 5;        // 0..7
            __half2* dst = (__half2*)(g_rgbth + ((size_t)b * P_ + pbase) * CIN_)
                         + c2;
            #pragma unroll
            for (int r = 0; r < 8; r++) {
                int p = prow * 8 + r;
                dst[(size_t)p * 32] =
                    __floats2half2_rn(ts[2 * c2][p], ts[2 * c2 + 1][p]);
            }
        }
    } else {
        int idx = (bid - 512) * 256 + tid;     // exactly KP_*COUT_ = 36864
        int m  = idx & 127;
        int kp = idx >> 7;
        int ck0 = 2 * kp, ck1 = 2 * kp + 1;
        int k0 = ck0 >> 6, c0 = ck0 & 63;
        int k1 = ck1 >> 6, c1 = ck1 & 63;
        __half h0 = __float2half(weight[(size_t)m * CK_ + c0 * K_ + k0]);
        __half h1 = __float2half(weight[(size_t)m * CK_ + c1 * K_ + k1]);
        uint32_t u = (uint32_t)__half_as_ushort(h0) |
                     ((uint32_t)__half_as_ushort(h1) << 16);
        g_wt[(size_t)kp * COUT_ + mperm(m)] = u;
    }
}

// ---------------------------------------------------------------------------
// Kernel 1: deformable im2col v5 (unchanged from R8).
// ---------------------------------------------------------------------------
#define PT 128

__global__ __launch_bounds__(256)
void im2col_kernel(const float* __restrict__ offsets) {
    __shared__ float4 metaW[PT];
    __shared__ int4   metaI[PT];

    const int ptile = blockIdx.x;
    const int k     = blockIdx.y;
    const int b     = blockIdx.z;
    const int p0    = ptile * PT;
    const int tid   = threadIdx.x;
    const int lane  = tid & 31;
    const int w     = tid >> 5;

    if (tid < PT) {
        int p  = p0 + tid;
        int oy = p >> 6;
        int ox = p & 63;

        const float* offb = offsets + (size_t)b * 2 * K_ * P_;
        float dy = offb[(2 * k    ) * P_ + p];
        float dx = offb[(2 * k + 1) * P_ + p];

        float y = (float)(oy - 1 + k / KW_) + dy;
        float x = (float)(ox - 1 + k % KW_) + dx;

        float y0f = floorf(y), x0f = floorf(x);
        float fy = y - y0f,    fx = x - x0f;
        int y0 = (int)y0f, x0 = (int)x0f;
        int y1 = y0 + 1,   x1 = x0 + 1;

        float w00 = (1.f - fy) * (1.f - fx);
        float w01 = (1.f - fy) * fx;
        float w10 = fy * (1.f - fx);
        float w11 = fy * fx;

        bool vy0 = (y0 >= 0) & (y0 < H_);
        bool vy1 = (y1 >= 0) & (y1 < H_);
        bool vx0 = (x0 >= 0) & (x0 < W_);
        bool vx1 = (x1 >= 0) & (x1 < W_);
        if (!(vy0 & vx0)) w00 = 0.f;
        if (!(vy0 & vx1)) w01 = 0.f;
        if (!(vy1 & vx0)) w10 = 0.f;
        if (!(vy1 & vx1)) w11 = 0.f;

        int cy0 = min(max(y0, 0), H_ - 1);
        int cy1 = min(max(y1, 0), H_ - 1);
        int cx0 = min(max(x0, 0), W_ - 1);
        int cx1 = min(max(x1, 0), W_ - 1);

        metaW[tid] = make_float4(w00, w01, w10, w11);
        metaI[tid] = make_int4(cy0 * W_ + cx0, cy0 * W_ + cx1,
                               cy1 * W_ + cx0, cy1 * W_ + cx1);
    }
    __syncthreads();

    const __half* baseh = g_rgbth + (size_t)b * P_ * CIN_;
    #pragma unroll 4
    for (int i = 0; i < 16; i++) {
        int px = w * 16 + i;
        int p  = p0 + px;
        float4 wt = metaW[px];
        int4   ix = metaI[px];
        __half2 q00 = ((const __half2*)(baseh + (size_t)ix.x * CIN_))[lane];
        __half2 q01 = ((const __half2*)(baseh + (size_t)ix.y * CIN_))[lane];
        __half2 q10 = ((const __half2*)(baseh + (size_t)ix.z * CIN_))[lane];
        __half2 q11 = ((const __half2*)(baseh + (size_t)ix.w * CIN_))[lane];
        float2 f00 = __half22float2(q00);
        float2 f01 = __half22float2(q01);
        float2 f10 = __half22float2(q10);
        float2 f11 = __half22float2(q11);
        float vx = wt.x * f00.x + wt.y * f01.x + wt.z * f10.x + wt.w * f11.x;
        float vy = wt.x * f00.y + wt.y * f01.y + wt.z * f10.y + wt.w * f11.y;
        __half2* dst = (__half2*)(g_colh + ((size_t)b * P_ + p) * CK_ + k * 64);
        dst[lane] = __floats2half2_rn(vx, vy);
    }
}

// ---------------------------------------------------------------------------
// Kernel 2: FP16 tensor-core GEMM, cp.async pipelined.
// B: 3-stage ring, [pixel][kpair] layout (pad 12), 16B cp.async per thread.
// A: 2-stage, STS from prefetched regs.  One __syncthreads per k-tile.
// ---------------------------------------------------------------------------
#define BN 128
#define NKP 8
#define NT  (KP_ / NKP)     // 36
#define LDA 136
#define LDB 12              // Bs row pad (words): qq*12+rr covers all 32 banks

__global__ __launch_bounds__(256, 2)
void gemm_fp16_kernel(const float* __restrict__ bias,
                      float* __restrict__ out) {
    __shared__ uint32_t As[2][NKP][LDA];       // [kpair][m_perm]
    __shared__ uint32_t Bs[3][BN][LDB];        // [pixel][kpair]

    const int b   = blockIdx.z;
    const int n0  = blockIdx.x * BN;
    const int tid = threadIdx.x;
    const int lane = tid & 31;
    const int wid  = tid >> 5;
    const int m_off = (wid >> 2) * 64;
    const int n_off = (wid & 3) * 32;
    const int qq = lane >> 2;
    const int rr = lane & 3;

    const __half* colb = g_colh + (size_t)b * P_ * CK_;   // [p][ck']
    const uint4*  wt4  = (const uint4*)g_wt;

    // producers
    const int prow = wid;            // A: kpair row 0..7
    const int pseg = lane;           // A: 4-word segment
    const int bpx  = tid >> 1;       // B: pixel 0..127
    const int bseg = tid & 1;        // B: 16B half of 32B k-slice

    const uint32_t bs_base = (uint32_t)__cvta_generic_to_shared(&Bs[0][0][0]);
    const uint32_t bdst    = bs_base + ((bpx * LDB + bseg * 4) << 2);
    const uint32_t bstage  = (BN * LDB) << 2;
    const __half*  bsrc    = colb + (size_t)(n0 + bpx) * CK_ + bseg * 8;

    float acc[4][4][4];
    #pragma unroll
    for (int i = 0; i < 4; i++)
        #pragma unroll
        for (int j = 0; j < 4; j++)
            #pragma unroll
            for (int c = 0; c < 4; c++) acc[i][j][c] = 0.f;

    // ---- prologue ----
    uint4 pa = wt4[(size_t)prow * 32 + pseg];
    *(uint4*)&As[0][prow][pseg * 4] = pa;              // A tile 0
    cp16(bdst,          bsrc);                          // B tile 0
    cp_commit();
    cp16(bdst + bstage, bsrc + 16);                     // B tile 1 (+16 halves)
    cp_commit();
    pa = wt4[(size_t)(NKP + prow) * 32 + pseg];         // A tile 1 -> regs

    for (int t = 0; t < NT; t++) {
        cp_wait<1>();          // B tile t resident
        __syncthreads();       // all warps past tile t-1 reads

        // stage A tile t+1 from regs; prefetch A tile t+2; issue B tile t+2
        if (t + 1 < NT)
            *(uint4*)&As[(t + 1) & 1][prow][pseg * 4] = pa;
        if (t + 2 < NT) {
            pa = wt4[(size_t)((t + 2) * NKP + prow) * 32 + pseg];
            cp16(bdst + ((t + 2) % 3) * bstage, bsrc + (t + 2) * 16);
        }
        cp_commit();           // always commit (possibly empty group)

        const int sa = t & 1;
        const int sb = t % 3;

        uint32_t bf[4][2];
        #pragma unroll
        for (int bn = 0; bn < 4; bn++) {
            bf[bn][0] = Bs[sb][n_off + 8 * bn + qq][rr];
            bf[bn][1] = Bs[sb][n_off + 8 * bn + qq][rr + 4];
        }
        uint32_t af[4][4];
        #pragma unroll
        for (int am = 0; am < 4; am++) {
            uint2 v0 = *(const uint2*)&As[sa][rr    ][m_off + 16 * am + 2 * qq];
            uint2 v1 = *(const uint2*)&As[sa][rr + 4][m_off + 16 * am + 2 * qq];
            af[am][0] = v0.x; af[am][1] = v0.y;
            af[am][2] = v1.x; af[am][3] = v1.y;
        }
        #pragma unroll
        for (int am = 0; am < 4; am++)
            #pragma unroll
            for (int bn = 0; bn < 4; bn++) {
                asm volatile(
                    "mma.sync.aligned.m16n8k16.row.col.f32.f16.f16.f32 "
                    "{%0,%1,%2,%3}, {%4,%5,%6,%7}, {%8,%9}, {%0,%1,%2,%3};"
                    : "+f"(acc[am][bn][0]), "+f"(acc[am][bn][1]),
                      "+f"(acc[am][bn][2]), "+f"(acc[am][bn][3])
                    : "r"(af[am][0]), "r"(af[am][1]),
                      "r"(af[am][2]), "r"(af[am][3]),
                      "r"(bf[bn][0]), "r"(bf[bn][1]));
            }
    }

    float* outb = out + (size_t)b * COUT_ * P_;
    #pragma unroll
    for (int am = 0; am < 4; am++) {
        int m0r = m_off + 16 * am + qq;
        float bv0 = bias[m0r];
        float bv1 = bias[m0r + 8];
        #pragma unroll
        for (int bn = 0; bn < 4; bn++) {
            int col = n0 + n_off + 8 * bn + 2 * rr;
            float2 v0 = make_float2(acc[am][bn][0] + bv0, acc[am][bn][1] + bv0);
            float2 v1 = make_float2(acc[am][bn][2] + bv1, acc[am][bn][3] + bv1);
            *(float2*)&outb[(size_t)m0r * P_ + col]       = v0;
            *(float2*)&outb[(size_t)(m0r + 8) * P_ + col] = v1;
        }
    }
}

extern "C" void kernel_launch(void* const* d_in, const int* in_sizes, int n_in,
                              void* d_out, int out_size) {
    const float* rgb     = (const float*)d_in[0];
    const float* offsets = (const float*)d_in[1];
    const float* weight  = (const float*)d_in[2];
    const float* bias    = (const float*)d_in[3];
    float* out = (float*)d_out;

    prep_kernel<<<656, 256>>>(rgb, weight);
    {
        dim3 grid(P_ / PT, K_, B_);          // 32 x 9 x 8
        im2col_kernel<<<grid, 256>>>(offsets);
    }
    {
        dim3 grid(P_ / BN, 1, B_);           // 32 x 1 x 8
        gemm_fp16_kernel<<<grid, 256>>>(bias, out);
    }
}

// round 10
// speedup vs baseline: 2.0665x; 1.1436x over previous
#include <cuda_runtime.h>
#include <cuda_fp16.h>
#include <math.h>
#include <stdint.h>

// Problem constants
#define B_     8
#define CIN_   64
#define COUT_  128
#define KH_    3
#define KW_    3
#define K_     9
#define H_     64
#define W_     64
#define P_     4096        // H*W
#define CK_    576         // CIN*K
#define KP_    288         // CK/2 k-pairs

// Scratch (static __device__ -> allocation-guard safe)
__device__ __half    g_rgbth[B_ * P_ * CIN_];    // fp16 [b][p][c]  4.2 MB
__device__ __half    g_colh[B_ * P_ * CK_];      // fp16 col [b][p][ck'], ck'=k*64+c
__device__ uint32_t  g_wt[KP_ * COUT_];          // weight packed half2 (kpair, m_perm)

__device__ __forceinline__ int mperm(int m) {
    return (m & ~15) | (((m & 7) << 1) | ((m >> 3) & 1));
}

__device__ __forceinline__ void cp16(uint32_t smem_addr, const void* gptr) {
    asm volatile("cp.async.ca.shared.global [%0], [%1], 16;"
                 :: "r"(smem_addr), "l"(gptr));
}
__device__ __forceinline__ void cp_commit() {
    asm volatile("cp.async.commit_group;");
}
template<int N>
__device__ __forceinline__ void cp_wait() {
    asm volatile("cp.async.wait_group %0;" :: "n"(N));
}

// fp32 bilinear blend of one half2 channel-pair from 4 corners
__device__ __forceinline__ uint32_t blend2(uint32_t a, uint32_t b,
                                           uint32_t c, uint32_t d,
                                           float4 wt) {
    float2 fa = __half22float2(*(__half2*)&a);
    float2 fb = __half22float2(*(__half2*)&b);
    float2 fc = __half22float2(*(__half2*)&c);
    float2 fd = __half22float2(*(__half2*)&d);
    float vx = wt.x * fa.x + wt.y * fb.x + wt.z * fc.x + wt.w * fd.x;
    float vy = wt.x * fa.y + wt.y * fb.y + wt.z * fc.y + wt.w * fd.y;
    __half2 h = __floats2half2_rn(vx, vy);
    return *(uint32_t*)&h;
}

// ---------------------------------------------------------------------------
// Kernel 0 (merged): blocks [0,512) transpose rgb fp32 [c][p] -> fp16 [p][c];
//                    blocks [512,656) pack weight to half2 (kpair, m_perm).
// ---------------------------------------------------------------------------
__global__ __launch_bounds__(256)
void prep_kernel(const float* __restrict__ rgb,
                 const float* __restrict__ weight) {
    const int bid = blockIdx.x;
    const int tid = threadIdx.x;

    if (bid < 512) {
        __shared__ float ts[64][65];
        const int b     = bid >> 6;
        const int pbase = (bid & 63) * 64;

        // load: float4 along p, coalesced (16 thr * 16B = 256B per c-row)
        {
            int pq = tid & 15;       // p-quad
            int cl = tid >> 4;       // 0..15
            #pragma unroll
            for (int it = 0; it < 4; it++) {
                int c = it * 16 + cl;
                float4 v = *(const float4*)(rgb + ((size_t)b * CIN_ + c) * P_
                                            + pbase + pq * 4);
                ts[c][pq * 4 + 0] = v.x;
                ts[c][pq * 4 + 1] = v.y;
                ts[c][pq * 4 + 2] = v.z;
                ts[c][pq * 4 + 3] = v.w;
            }
        }
        __syncthreads();

        // store: 8 fp16 channels per STG.128, contiguous in [p][c]
        {
            int cg = tid & 7;        // channel group (8 ch)
            int pr = tid >> 3;       // 0..31
            #pragma unroll
            for (int it = 0; it < 2; it++) {
                int p = it * 32 + pr;
                __half2 h0 = __floats2half2_rn(ts[cg*8+0][p], ts[cg*8+1][p]);
                __half2 h1 = __floats2half2_rn(ts[cg*8+2][p], ts[cg*8+3][p]);
                __half2 h2 = __floats2half2_rn(ts[cg*8+4][p], ts[cg*8+5][p]);
                __half2 h3 = __floats2half2_rn(ts[cg*8+6][p], ts[cg*8+7][p]);
                uint4 u = make_uint4(*(uint32_t*)&h0, *(uint32_t*)&h1,
                                     *(uint32_t*)&h2, *(uint32_t*)&h3);
                *(uint4*)(g_rgbth + ((size_t)b * P_ + pbase + p) * CIN_
                          + cg * 8) = u;
            }
        }
    } else {
        int idx = (bid - 512) * 256 + tid;     // exactly KP_*COUT_ = 36864
        int m  = idx & 127;
        int kp = idx >> 7;
        int ck0 = 2 * kp, ck1 = 2 * kp + 1;
        int k0 = ck0 >> 6, c0 = ck0 & 63;
        int k1 = ck1 >> 6, c1 = ck1 & 63;
        __half h0 = __float2half(weight[(size_t)m * CK_ + c0 * K_ + k0]);
        __half h1 = __float2half(weight[(size_t)m * CK_ + c1 * K_ + k1]);
        uint32_t u = (uint32_t)__half_as_ushort(h0) |
                     ((uint32_t)__half_as_ushort(h1) << 16);
        g_wt[(size_t)kp * COUT_ + mperm(m)] = u;
    }
}

// ---------------------------------------------------------------------------
// Kernel 1: deformable im2col v6.
// Block = (b, k, 128-pixel tile). 4 pixels per warp-group, lane = 8-channel
// uint4. Per 4 pixels: 4 LDG.128 + 1 STG.128 + meta. fp32 interpolation.
// ---------------------------------------------------------------------------
#define PT 128

__global__ __launch_bounds__(256)
void im2col_kernel(const float* __restrict__ offsets) {
    __shared__ float4 metaW[PT];
    __shared__ int4   metaI[PT];

    const int ptile = blockIdx.x;
    const int k     = blockIdx.y;
    const int b     = blockIdx.z;
    const int p0    = ptile * PT;
    const int tid   = threadIdx.x;
    const int lane  = tid & 31;
    const int w     = tid >> 5;

    // ---- Phase 1: bilinear meta for 128 pixels ----
    if (tid < PT) {
        int p  = p0 + tid;
        int oy = p >> 6;
        int ox = p & 63;

        const float* offb = offsets + (size_t)b * 2 * K_ * P_;
        float dy = offb[(2 * k    ) * P_ + p];
        float dx = offb[(2 * k + 1) * P_ + p];

        float y = (float)(oy - 1 + k / KW_) + dy;
        float x = (float)(ox - 1 + k % KW_) + dx;

        float y0f = floorf(y), x0f = floorf(x);
        float fy = y - y0f,    fx = x - x0f;
        int y0 = (int)y0f, x0 = (int)x0f;
        int y1 = y0 + 1,   x1 = x0 + 1;

        float w00 = (1.f - fy) * (1.f - fx);
        float w01 = (1.f - fy) * fx;
        float w10 = fy * (1.f - fx);
        float w11 = fy * fx;

        bool vy0 = (y0 >= 0) & (y0 < H_);
        bool vy1 = (y1 >= 0) & (y1 < H_);
        bool vx0 = (x0 >= 0) & (x0 < W_);
        bool vx1 = (x1 >= 0) & (x1 < W_);
        if (!(vy0 & vx0)) w00 = 0.f;
        if (!(vy0 & vx1)) w01 = 0.f;
        if (!(vy1 & vx0)) w10 = 0.f;
        if (!(vy1 & vx1)) w11 = 0.f;

        int cy0 = min(max(y0, 0), H_ - 1);
        int cy1 = min(max(y1, 0), H_ - 1);
        int cx0 = min(max(x0, 0), W_ - 1);
        int cx1 = min(max(x1, 0), W_ - 1);

        metaW[tid] = make_float4(w00, w01, w10, w11);
        metaI[tid] = make_int4(cy0 * W_ + cx0, cy0 * W_ + cx1,
                               cy1 * W_ + cx0, cy1 * W_ + cx1);
    }
    __syncthreads();

    // ---- Phase 2: 4 pixels per warp-group iteration ----
    const __half* baseh = g_rgbth + (size_t)b * P_ * CIN_;
    const int ln8 = lane & 7;
    const int sub = lane >> 3;           // 0..3: which pixel in group

    #pragma unroll
    for (int g = 0; g < 4; g++) {
        int px = w * 16 + g * 4 + sub;
        int p  = p0 + px;
        float4 wt = metaW[px];
        int4   ix = metaI[px];
        uint4 q00 = ((const uint4*)(baseh + (size_t)ix.x * CIN_))[ln8];
        uint4 q01 = ((const uint4*)(baseh + (size_t)ix.y * CIN_))[ln8];
        uint4 q10 = ((const uint4*)(baseh + (size_t)ix.z * CIN_))[ln8];
        uint4 q11 = ((const uint4*)(baseh + (size_t)ix.w * CIN_))[ln8];
        uint4 r;
        r.x = blend2(q00.x, q01.x, q10.x, q11.x, wt);
        r.y = blend2(q00.y, q01.y, q10.y, q11.y, wt);
        r.z = blend2(q00.z, q01.z, q10.z, q11.z, wt);
        r.w = blend2(q00.w, q01.w, q10.w, q11.w, wt);
        ((uint4*)(g_colh + ((size_t)b * P_ + p) * CK_ + k * 64))[ln8] = r;
    }
}

// ---------------------------------------------------------------------------
// Kernel 2: FP16 tensor-core GEMM, cp.async pipelined.  (unchanged from R9)
// ---------------------------------------------------------------------------
#define BN 128
#define NKP 8
#define NT  (KP_ / NKP)     // 36
#define LDA 136
#define LDB 12

__global__ __launch_bounds__(256, 2)
void gemm_fp16_kernel(const float* __restrict__ bias,
                      float* __restrict__ out) {
    __shared__ uint32_t As[2][NKP][LDA];       // [kpair][m_perm]
    __shared__ uint32_t Bs[3][BN][LDB];        // [pixel][kpair]

    const int b   = blockIdx.z;
    const int n0  = blockIdx.x * BN;
    const int tid = threadIdx.x;
    const int lane = tid & 31;
    const int wid  = tid >> 5;
    const int m_off = (wid >> 2) * 64;
    const int n_off = (wid & 3) * 32;
    const int qq = lane >> 2;
    const int rr = lane & 3;

    const __half* colb = g_colh + (size_t)b * P_ * CK_;   // [p][ck']
    const uint4*  wt4  = (const uint4*)g_wt;

    const int prow = wid;
    const int pseg = lane;
    const int bpx  = tid >> 1;
    const int bseg = tid & 1;

    const uint32_t bs_base = (uint32_t)__cvta_generic_to_shared(&Bs[0][0][0]);
    const uint32_t bdst    = bs_base + ((bpx * LDB + bseg * 4) << 2);
    const uint32_t bstage  = (BN * LDB) << 2;
    const __half*  bsrc    = colb + (size_t)(n0 + bpx) * CK_ + bseg * 8;

    float acc[4][4][4];
    #pragma unroll
    for (int i = 0; i < 4; i++)
        #pragma unroll
        for (int j = 0; j < 4; j++)
            #pragma unroll
            for (int c = 0; c < 4; c++) acc[i][j][c] = 0.f;

    uint4 pa = wt4[(size_t)prow * 32 + pseg];
    *(uint4*)&As[0][prow][pseg * 4] = pa;
    cp16(bdst,          bsrc);
    cp_commit();
    cp16(bdst + bstage, bsrc + 16);
    cp_commit();
    pa = wt4[(size_t)(NKP + prow) * 32 + pseg];

    for (int t = 0; t < NT; t++) {
        cp_wait<1>();
        __syncthreads();

        if (t + 1 < NT)
            *(uint4*)&As[(t + 1) & 1][prow][pseg * 4] = pa;
        if (t + 2 < NT) {
            pa = wt4[(size_t)((t + 2) * NKP + prow) * 32 + pseg];
            cp16(bdst + ((t + 2) % 3) * bstage, bsrc + (t + 2) * 16);
        }
        cp_commit();

        const int sa = t & 1;
        const int sb = t % 3;

        uint32_t bf[4][2];
        #pragma unroll
        for (int bn = 0; bn < 4; bn++) {
            bf[bn][0] = Bs[sb][n_off + 8 * bn + qq][rr];
            bf[bn][1] = Bs[sb][n_off + 8 * bn + qq][rr + 4];
        }
        uint32_t af[4][4];
        #pragma unroll
        for (int am = 0; am < 4; am++) {
            uint2 v0 = *(const uint2*)&As[sa][rr    ][m_off + 16 * am + 2 * qq];
            uint2 v1 = *(const uint2*)&As[sa][rr + 4][m_off + 16 * am + 2 * qq];
            af[am][0] = v0.x; af[am][1] = v0.y;
            af[am][2] = v1.x; af[am][3] = v1.y;
        }
        #pragma unroll
        for (int am = 0; am < 4; am++)
            #pragma unroll
            for (int bn = 0; bn < 4; bn++) {
                asm volatile(
                    "mma.sync.aligned.m16n8k16.row.col.f32.f16.f16.f32 "
                    "{%0,%1,%2,%3}, {%4,%5,%6,%7}, {%8,%9}, {%0,%1,%2,%3};"
                    : "+f"(acc[am][bn][0]), "+f"(acc[am][bn][1]),
                      "+f"(acc[am][bn][2]), "+f"(acc[am][bn][3])
                    : "r"(af[am][0]), "r"(af[am][1]),
                      "r"(af[am][2]), "r"(af[am][3]),
                      "r"(bf[bn][0]), "r"(bf[bn][1]));
            }
    }

    float* outb = out + (size_t)b * COUT_ * P_;
    #pragma unroll
    for (int am = 0; am < 4; am++) {
        int m0r = m_off + 16 * am + qq;
        float bv0 = bias[m0r];
        float bv1 = bias[m0r + 8];
        #pragma unroll
        for (int bn = 0; bn < 4; bn++) {
            int col = n0 + n_off + 8 * bn + 2 * rr;
            float2 v0 = make_float2(acc[am][bn][0] + bv0, acc[am][bn][1] + bv0);
            float2 v1 = make_float2(acc[am][bn][2] + bv1, acc[am][bn][3] + bv1);
            *(float2*)&outb[(size_t)m0r * P_ + col]       = v0;
            *(float2*)&outb[(size_t)(m0r + 8) * P_ + col] = v1;
        }
    }
}

extern "C" void kernel_launch(void* const* d_in, const int* in_sizes, int n_in,
                              void* d_out, int out_size) {
    const float* rgb     = (const float*)d_in[0];
    const float* offsets = (const float*)d_in[1];
    const float* weight  = (const float*)d_in[2];
    const float* bias    = (const float*)d_in[3];
    float* out = (float*)d_out;

    prep_kernel<<<656, 256>>>(rgb, weight);
    {
        dim3 grid(P_ / PT, K_, B_);          // 32 x 9 x 8
        im2col_kernel<<<grid, 256>>>(offsets);
    }
    {
        dim3 grid(P_ / BN, 1, B_);           // 32 x 1 x 8
        gemm_fp16_kernel<<<grid, 256>>>(bias, out);
    }
}